// round 9
// baseline (speedup 1.0000x reference)
#include <cuda_runtime.h>
#include <cuda_bf16.h>
#include <cstdint>

#define B_   8
#define C_   256
#define H_   96
#define W_   96
#define HW_  (H_*W_)          // 9216
#define G_   4
#define CG_  64
#define HO_  192
#define WO_  192
#define HOWO_ (HO_*WO_)
#define NOUT_ 32

// Scratch coords (ix, iy) per output pixel, layout [n][oy][ox]
__device__ __align__(16) float2 g_coords[B_ * G_ * HO_ * WO_];   // 9.4 MB

// ---------------------------------------------------------------------------
// Kernel 1: offset head GEMV (R1 shape: 192 thr = 96x2, grid 48x8, unroll 2).
// ---------------------------------------------------------------------------
__global__ __launch_bounds__(192) void dysample_offset_kernel(
    const float* __restrict__ x,
    const float* __restrict__ w_off,
    const float* __restrict__ b_off)
{
    __shared__ __align__(16) float w_sh[NOUT_ * C_];   // 32 KB
    __shared__ float b_sh[NOUT_];

    const int tid = threadIdx.y * 96 + threadIdx.x;
    for (int i = tid; i < NOUT_ * C_; i += 192) w_sh[i] = w_off[i];
    if (tid < NOUT_) b_sh[tid] = b_off[tid];
    __syncthreads();

    const int b = blockIdx.y;
    const int h = blockIdx.x * 2 + threadIdx.y;
    const int w = threadIdx.x;

    const float* xp = x + (size_t)b * C_ * HW_ + h * W_ + w;

    float acc[NOUT_];
#pragma unroll
    for (int o = 0; o < NOUT_; o++) acc[o] = 0.f;

#pragma unroll 2
    for (int cb = 0; cb < C_; cb += 4) {
        const float xv0 = xp[(cb + 0) * HW_];
        const float xv1 = xp[(cb + 1) * HW_];
        const float xv2 = xp[(cb + 2) * HW_];
        const float xv3 = xp[(cb + 3) * HW_];
#pragma unroll
        for (int o = 0; o < NOUT_; o++) {
            const float4 wv = *(const float4*)&w_sh[o * C_ + cb];
            float t = acc[o];
            t = fmaf(xv0, wv.x, t);
            t = fmaf(xv1, wv.y, t);
            t = fmaf(xv2, wv.z, t);
            t = fmaf(xv3, wv.w, t);
            acc[o] = t;
        }
    }

    const float wf = (float)w;
    const float hf = (float)h;
#pragma unroll
    for (int gi = 0; gi < G_; gi++) {
#pragma unroll
        for (int sy = 0; sy < 2; sy++) {
#pragma unroll
            for (int sx = 0; sx < 2; sx++) {
                const int idx = gi * 4 + sy * 2 + sx;
                float ix = wf + (acc[idx]      + b_sh[idx])      * 0.25f;
                float iy = hf + (acc[16 + idx] + b_sh[16 + idx]) * 0.25f;
                ix = fminf(fmaxf(ix, 0.f), (float)(W_ - 1));
                iy = fminf(fmaxf(iy, 0.f), (float)(H_ - 1));
                const int n  = b * G_ + gi;
                const int oy = 2 * h + sy;
                const int ox = 2 * w + sx;
                g_coords[((size_t)n * HO_ + oy) * WO_ + ox] = make_float2(ix, iy);
            }
        }
    }
}

// ---------------------------------------------------------------------------
// Kernel 2: one thread = 2x2 output block (oy=2h..2h+1, ox=2q..2q+1).
// Loads a 3x3 input stencil around (h,q) once per channel; each pixel's
// bilinear = u^T S v with zero-padded 3-vectors (pure FMA, no selects).
// Fallback to direct global gather if any tap leaves the stencil.
// ---------------------------------------------------------------------------
__global__ __launch_bounds__(256) void dysample_sample_kernel(
    const float* __restrict__ x,
    float* __restrict__ out)
{
    const int g  = blockIdx.x * 256 + threadIdx.x;    // 0 .. 294911
    const int q  = g % W_;
    const int t1 = g / W_;
    const int h  = t1 % H_;
    const int n  = t1 / H_;
    const int b  = n >> 2;
    const int gi = n & 3;

    // 4 pixel coords (two float4 loads)
    const float4 cT = *(const float4*)&g_coords[((size_t)n * HO_ + 2 * h) * WO_ + 2 * q];
    const float4 cB = *(const float4*)&g_coords[((size_t)n * HO_ + 2 * h + 1) * WO_ + 2 * q];

    // Per-pixel u,v 3-vectors
    float v0[4], v1[4], v2[4], u0[4], u1[4], u2[4];
    bool ok = true;
    const float pix[4][2] = {{cT.x, cT.y}, {cT.z, cT.w}, {cB.x, cB.y}, {cB.z, cB.w}};
    int xi0s[4], yi0s[4];
#pragma unroll
    for (int k = 0; k < 4; k++) {
        const float ix = pix[k][0], iy = pix[k][1];
        const float x0f = floorf(ix), y0f = floorf(iy);
        const int xi0 = (int)x0f, yi0 = (int)y0f;
        xi0s[k] = xi0; yi0s[k] = yi0;
        const float wx = ix - x0f, wy = iy - y0f;
        const int dx = xi0 - (q - 1);
        const int dy = yi0 - (h - 1);
        ok = ok && (dx >= 0) && (dx <= 1) && (dy >= 0) && (dy <= 1);
        const float ax = (float)dx, ay = (float)dy;
        v0[k] = (1.f - wx) * (1.f - ax);
        v1[k] = fmaf(-2.f * ax, wx, wx + ax);
        v2[k] = ax * wx;
        u0[k] = (1.f - wy) * (1.f - ay);
        u1[k] = fmaf(-2.f * ay, wy, wy + ay);
        u2[k] = ay * wy;
    }

    const float* __restrict__ base = x + (size_t)(b * C_ + gi * CG_) * HW_;
    float* __restrict__ oT = out + ((size_t)(b * C_ + gi * CG_) * HO_ + 2 * h) * WO_ + 2 * q;
    float* __restrict__ oB = oT + WO_;

    if (ok) {
        // 9 stencil pointers (clamped rows/cols)
        const int r0 = max(h - 1, 0), r1 = h, r2 = min(h + 1, H_ - 1);
        const int c0 = max(q - 1, 0), c1 = q, c2 = min(q + 1, W_ - 1);
        const float* p00 = base + r0 * W_ + c0;
        const float* p01 = base + r0 * W_ + c1;
        const float* p02 = base + r0 * W_ + c2;
        const float* p10 = base + r1 * W_ + c0;
        const float* p11 = base + r1 * W_ + c1;
        const float* p12 = base + r1 * W_ + c2;
        const float* p20 = base + r2 * W_ + c0;
        const float* p21 = base + r2 * W_ + c1;
        const float* p22 = base + r2 * W_ + c2;

#pragma unroll 1
        for (int cb = 0; cb < CG_; cb += 4) {
#pragma unroll
            for (int cc = 0; cc < 4; cc++) {
                const int o = cc * HW_;                 // SASS immediate
                const float s00 = __ldg(p00 + o);
                const float s01 = __ldg(p01 + o);
                const float s02 = __ldg(p02 + o);
                const float s10 = __ldg(p10 + o);
                const float s11 = __ldg(p11 + o);
                const float s12 = __ldg(p12 + o);
                const float s20 = __ldg(p20 + o);
                const float s21 = __ldg(p21 + o);
                const float s22 = __ldg(p22 + o);

                float res[4];
#pragma unroll
                for (int k = 0; k < 4; k++) {
                    float t0 = s00 * v0[k];
                    t0 = fmaf(s01, v1[k], t0);
                    t0 = fmaf(s02, v2[k], t0);
                    float t1r = s10 * v0[k];
                    t1r = fmaf(s11, v1[k], t1r);
                    t1r = fmaf(s12, v2[k], t1r);
                    float t2 = s20 * v0[k];
                    t2 = fmaf(s21, v1[k], t2);
                    t2 = fmaf(s22, v2[k], t2);
                    float r = t0 * u0[k];
                    r = fmaf(t1r, u1[k], r);
                    r = fmaf(t2, u2[k], r);
                    res[k] = r;
                }
                const size_t oo = (size_t)cc * HOWO_;
                *(float2*)(oT + oo) = make_float2(res[0], res[1]);
                *(float2*)(oB + oo) = make_float2(res[2], res[3]);
            }
            p00 += 4 * HW_; p01 += 4 * HW_; p02 += 4 * HW_;
            p10 += 4 * HW_; p11 += 4 * HW_; p12 += 4 * HW_;
            p20 += 4 * HW_; p21 += 4 * HW_; p22 += 4 * HW_;
            oT  += (size_t)4 * HOWO_;
            oB  += (size_t)4 * HOWO_;
        }
    } else {
        // Rare fallback: direct gather per pixel (exact, any offset magnitude)
#pragma unroll
        for (int k = 0; k < 4; k++) {
            const float ix = pix[k][0], iy = pix[k][1];
            const float x0f = floorf(ix), y0f = floorf(iy);
            const float wx = ix - x0f, wy = iy - y0f;
            const int xi0 = xi0s[k], yi0 = yi0s[k];
            const int xi1 = min(xi0 + 1, W_ - 1);
            const int yi1 = min(yi0 + 1, H_ - 1);
            const float w00 = (1.f - wy) * (1.f - wx);
            const float w01 = (1.f - wy) * wx;
            const float w10 = wy * (1.f - wx);
            const float w11 = wy * wx;
            const float* g00 = base + yi0 * W_ + xi0;
            const float* g01 = base + yi0 * W_ + xi1;
            const float* g10 = base + yi1 * W_ + xi0;
            const float* g11 = base + yi1 * W_ + xi1;
            float* op = ((k & 2) ? oB : oT) + (k & 1);
#pragma unroll 4
            for (int c = 0; c < CG_; c++) {
                float v = w00 * __ldg(g00 + c * HW_);
                v = fmaf(w01, __ldg(g01 + c * HW_), v);
                v = fmaf(w10, __ldg(g10 + c * HW_), v);
                v = fmaf(w11, __ldg(g11 + c * HW_), v);
                op[(size_t)c * HOWO_] = v;
            }
        }
    }
}

// ---------------------------------------------------------------------------
extern "C" void kernel_launch(void* const* d_in, const int* in_sizes, int n_in,
                              void* d_out, int out_size)
{
    const float* x     = (const float*)d_in[0];
    const float* w_off = (const float*)d_in[1];
    const float* b_off = (const float*)d_in[2];
    float* out = (float*)d_out;

    dysample_offset_kernel<<<dim3(48, B_), dim3(96, 2)>>>(x, w_off, b_off);
    dysample_sample_kernel<<<(B_ * G_ * H_ * W_) / 256, 256>>>(x, out);
}

// round 10
// speedup vs baseline: 1.0005x; 1.0005x over previous
#include <cuda_runtime.h>
#include <cuda_bf16.h>
#include <cstdint>

#define B_   8
#define C_   256
#define H_   96
#define W_   96
#define HW_  (H_*W_)          // 9216
#define G_   4
#define CG_  64
#define HO_  192
#define WO_  192
#define HOWO_ (HO_*WO_)
#define NOUT_ 32

// Scratch coords (ix, iy) per output pixel, layout [n][oy][ox]
__device__ __align__(16) float2 g_coords[B_ * G_ * HO_ * WO_];   // 9.4 MB

// ---------------------------------------------------------------------------
// Kernel 1: offset head GEMV (R1 shape: 192 thr = 96x2, grid 48x8, unroll 2).
// ---------------------------------------------------------------------------
__global__ __launch_bounds__(192) void dysample_offset_kernel(
    const float* __restrict__ x,
    const float* __restrict__ w_off,
    const float* __restrict__ b_off)
{
    __shared__ __align__(16) float w_sh[NOUT_ * C_];   // 32 KB
    __shared__ float b_sh[NOUT_];

    const int tid = threadIdx.y * 96 + threadIdx.x;
    for (int i = tid; i < NOUT_ * C_; i += 192) w_sh[i] = w_off[i];
    if (tid < NOUT_) b_sh[tid] = b_off[tid];
    __syncthreads();

    const int b = blockIdx.y;
    const int h = blockIdx.x * 2 + threadIdx.y;
    const int w = threadIdx.x;

    const float* xp = x + (size_t)b * C_ * HW_ + h * W_ + w;

    float acc[NOUT_];
#pragma unroll
    for (int o = 0; o < NOUT_; o++) acc[o] = 0.f;

#pragma unroll 2
    for (int cb = 0; cb < C_; cb += 4) {
        const float xv0 = xp[(cb + 0) * HW_];
        const float xv1 = xp[(cb + 1) * HW_];
        const float xv2 = xp[(cb + 2) * HW_];
        const float xv3 = xp[(cb + 3) * HW_];
#pragma unroll
        for (int o = 0; o < NOUT_; o++) {
            const float4 wv = *(const float4*)&w_sh[o * C_ + cb];
            float t = acc[o];
            t = fmaf(xv0, wv.x, t);
            t = fmaf(xv1, wv.y, t);
            t = fmaf(xv2, wv.z, t);
            t = fmaf(xv3, wv.w, t);
            acc[o] = t;
        }
    }

    const float wf = (float)w;
    const float hf = (float)h;
#pragma unroll
    for (int gi = 0; gi < G_; gi++) {
#pragma unroll
        for (int sy = 0; sy < 2; sy++) {
#pragma unroll
            for (int sx = 0; sx < 2; sx++) {
                const int idx = gi * 4 + sy * 2 + sx;
                float ix = wf + (acc[idx]      + b_sh[idx])      * 0.25f;
                float iy = hf + (acc[16 + idx] + b_sh[16 + idx]) * 0.25f;
                ix = fminf(fmaxf(ix, 0.f), (float)(W_ - 1));
                iy = fminf(fmaxf(iy, 0.f), (float)(H_ - 1));
                const int n  = b * G_ + gi;
                const int oy = 2 * h + sy;
                const int ox = 2 * w + sx;
                g_coords[((size_t)n * HO_ + oy) * WO_ + ox] = make_float2(ix, iy);
            }
        }
    }
}

// ---------------------------------------------------------------------------
// Kernel 2: one thread = 2x2 output block (oy=2h..2h+1, ox=2q..2q+1).
// Loads a 3x3 input stencil around (h,q) once per channel; each pixel's
// bilinear = u^T S v with zero-padded 3-vectors (pure FMA, no selects).
// Fallback to direct global gather if any tap leaves the stencil.
// ---------------------------------------------------------------------------
__global__ __launch_bounds__(256) void dysample_sample_kernel(
    const float* __restrict__ x,
    float* __restrict__ out)
{
    const int g  = blockIdx.x * 256 + threadIdx.x;    // 0 .. 294911
    const int q  = g % W_;
    const int t1 = g / W_;
    const int h  = t1 % H_;
    const int n  = t1 / H_;
    const int b  = n >> 2;
    const int gi = n & 3;

    // 4 pixel coords (two float4 loads)
    const float4 cT = *(const float4*)&g_coords[((size_t)n * HO_ + 2 * h) * WO_ + 2 * q];
    const float4 cB = *(const float4*)&g_coords[((size_t)n * HO_ + 2 * h + 1) * WO_ + 2 * q];

    // Per-pixel u,v 3-vectors
    float v0[4], v1[4], v2[4], u0[4], u1[4], u2[4];
    bool ok = true;
    const float pix[4][2] = {{cT.x, cT.y}, {cT.z, cT.w}, {cB.x, cB.y}, {cB.z, cB.w}};
    int xi0s[4], yi0s[4];
#pragma unroll
    for (int k = 0; k < 4; k++) {
        const float ix = pix[k][0], iy = pix[k][1];
        const float x0f = floorf(ix), y0f = floorf(iy);
        const int xi0 = (int)x0f, yi0 = (int)y0f;
        xi0s[k] = xi0; yi0s[k] = yi0;
        const float wx = ix - x0f, wy = iy - y0f;
        const int dx = xi0 - (q - 1);
        const int dy = yi0 - (h - 1);
        ok = ok && (dx >= 0) && (dx <= 1) && (dy >= 0) && (dy <= 1);
        const float ax = (float)dx, ay = (float)dy;
        v0[k] = (1.f - wx) * (1.f - ax);
        v1[k] = fmaf(-2.f * ax, wx, wx + ax);
        v2[k] = ax * wx;
        u0[k] = (1.f - wy) * (1.f - ay);
        u1[k] = fmaf(-2.f * ay, wy, wy + ay);
        u2[k] = ay * wy;
    }

    const float* __restrict__ base = x + (size_t)(b * C_ + gi * CG_) * HW_;
    float* __restrict__ oT = out + ((size_t)(b * C_ + gi * CG_) * HO_ + 2 * h) * WO_ + 2 * q;
    float* __restrict__ oB = oT + WO_;

    if (ok) {
        // 9 stencil pointers (clamped rows/cols)
        const int r0 = max(h - 1, 0), r1 = h, r2 = min(h + 1, H_ - 1);
        const int c0 = max(q - 1, 0), c1 = q, c2 = min(q + 1, W_ - 1);
        const float* p00 = base + r0 * W_ + c0;
        const float* p01 = base + r0 * W_ + c1;
        const float* p02 = base + r0 * W_ + c2;
        const float* p10 = base + r1 * W_ + c0;
        const float* p11 = base + r1 * W_ + c1;
        const float* p12 = base + r1 * W_ + c2;
        const float* p20 = base + r2 * W_ + c0;
        const float* p21 = base + r2 * W_ + c1;
        const float* p22 = base + r2 * W_ + c2;

#pragma unroll 1
        for (int cb = 0; cb < CG_; cb += 4) {
#pragma unroll
            for (int cc = 0; cc < 4; cc++) {
                const int o = cc * HW_;                 // SASS immediate
                const float s00 = __ldg(p00 + o);
                const float s01 = __ldg(p01 + o);
                const float s02 = __ldg(p02 + o);
                const float s10 = __ldg(p10 + o);
                const float s11 = __ldg(p11 + o);
                const float s12 = __ldg(p12 + o);
                const float s20 = __ldg(p20 + o);
                const float s21 = __ldg(p21 + o);
                const float s22 = __ldg(p22 + o);

                float res[4];
#pragma unroll
                for (int k = 0; k < 4; k++) {
                    float t0 = s00 * v0[k];
                    t0 = fmaf(s01, v1[k], t0);
                    t0 = fmaf(s02, v2[k], t0);
                    float t1r = s10 * v0[k];
                    t1r = fmaf(s11, v1[k], t1r);
                    t1r = fmaf(s12, v2[k], t1r);
                    float t2 = s20 * v0[k];
                    t2 = fmaf(s21, v1[k], t2);
                    t2 = fmaf(s22, v2[k], t2);
                    float r = t0 * u0[k];
                    r = fmaf(t1r, u1[k], r);
                    r = fmaf(t2, u2[k], r);
                    res[k] = r;
                }
                const size_t oo = (size_t)cc * HOWO_;
                *(float2*)(oT + oo) = make_float2(res[0], res[1]);
                *(float2*)(oB + oo) = make_float2(res[2], res[3]);
            }
            p00 += 4 * HW_; p01 += 4 * HW_; p02 += 4 * HW_;
            p10 += 4 * HW_; p11 += 4 * HW_; p12 += 4 * HW_;
            p20 += 4 * HW_; p21 += 4 * HW_; p22 += 4 * HW_;
            oT  += (size_t)4 * HOWO_;
            oB  += (size_t)4 * HOWO_;
        }
    } else {
        // Rare fallback: direct gather per pixel (exact, any offset magnitude)
#pragma unroll
        for (int k = 0; k < 4; k++) {
            const float ix = pix[k][0], iy = pix[k][1];
            const float x0f = floorf(ix), y0f = floorf(iy);
            const float wx = ix - x0f, wy = iy - y0f;
            const int xi0 = xi0s[k], yi0 = yi0s[k];
            const int xi1 = min(xi0 + 1, W_ - 1);
            const int yi1 = min(yi0 + 1, H_ - 1);
            const float w00 = (1.f - wy) * (1.f - wx);
            const float w01 = (1.f - wy) * wx;
            const float w10 = wy * (1.f - wx);
            const float w11 = wy * wx;
            const float* g00 = base + yi0 * W_ + xi0;
            const float* g01 = base + yi0 * W_ + xi1;
            const float* g10 = base + yi1 * W_ + xi0;
            const float* g11 = base + yi1 * W_ + xi1;
            float* op = ((k & 2) ? oB : oT) + (k & 1);
#pragma unroll 4
            for (int c = 0; c < CG_; c++) {
                float v = w00 * __ldg(g00 + c * HW_);
                v = fmaf(w01, __ldg(g01 + c * HW_), v);
                v = fmaf(w10, __ldg(g10 + c * HW_), v);
                v = fmaf(w11, __ldg(g11 + c * HW_), v);
                op[(size_t)c * HOWO_] = v;
            }
        }
    }
}

// ---------------------------------------------------------------------------
extern "C" void kernel_launch(void* const* d_in, const int* in_sizes, int n_in,
                              void* d_out, int out_size)
{
    const float* x     = (const float*)d_in[0];
    const float* w_off = (const float*)d_in[1];
    const float* b_off = (const float*)d_in[2];
    float* out = (float*)d_out;

    dysample_offset_kernel<<<dim3(48, B_), dim3(96, 2)>>>(x, w_off, b_off);
    dysample_sample_kernel<<<(B_ * G_ * H_ * W_) / 256, 256>>>(x, out);
}

// round 11
// speedup vs baseline: 1.2861x; 1.2855x over previous
#include <cuda_runtime.h>
#include <cuda_bf16.h>
#include <cstdint>

#define B_   8
#define C_   256
#define H_   96
#define W_   96
#define HW_  (H_*W_)          // 9216
#define G_   4
#define CG_  64
#define HO_  192
#define WO_  192
#define HOWO_ (HO_*WO_)
#define NOUT_ 32

// Scratch coords (ix, iy) per output pixel, layout [n][oy][ox]
__device__ __align__(16) float2 g_coords[B_ * G_ * HO_ * WO_];   // 9.4 MB

// ---------------------------------------------------------------------------
// Kernel 1: offset head as register-tiled GEMM.
// Block: 256 threads, 256 positions, all 32 outputs, K=256.
// Thread (og = tid/32, pg = tid%32) owns o in [4og,4og+4), pos in [8pg,8pg+8).
// x chunks [32 k][256 pos] staged in SMEM (double buffered, natural layout).
// Per k: 4 broadcast LDS.32 (w) + 2 LDS.128 (x) + 32 FFMA.
// ---------------------------------------------------------------------------
__global__ __launch_bounds__(256) void dysample_offset_kernel(
    const float* __restrict__ x,
    const float* __restrict__ w_off,
    const float* __restrict__ b_off)
{
    __shared__ __align__(16) float w_sh[NOUT_ * C_];     // 32 KB [o][k]
    __shared__ float b_sh[NOUT_];
    __shared__ __align__(16) float x_sh[2][32 * 256];    // 64 KB, [buf][k][pos]

    const int tid = threadIdx.x;
#pragma unroll
    for (int i = 0; i < 8; i++)
        ((float4*)w_sh)[tid + i * 256] = ((const float4*)w_off)[tid + i * 256];
    if (tid < NOUT_) b_sh[tid] = b_off[tid];

    const int pos0 = blockIdx.x * 256;      // 9216 % 256 == 0 -> single b
    const int b    = pos0 / HW_;
    const int posb = pos0 % HW_;
    const float* xb = x + (size_t)b * C_ * HW_ + posb;

    const int og = tid >> 5;                // 0..7  (o group of 4)
    const int pg = tid & 31;                // 0..31 (pos group of 8)

    float acc[4][8];
#pragma unroll
    for (int j = 0; j < 4; j++)
#pragma unroll
        for (int i = 0; i < 8; i++) acc[j][i] = 0.f;

    // Preload chunk 0 into buf 0
    float4 stage[8];
#pragma unroll
    for (int j = 0; j < 8; j++) {
        const int f4 = tid + j * 256;
        const int k  = f4 >> 6;
        const int p4 = f4 & 63;
        stage[j] = *(const float4*)(xb + (size_t)k * HW_ + p4 * 4);
    }
#pragma unroll
    for (int j = 0; j < 8; j++)
        ((float4*)x_sh[0])[tid + j * 256] = stage[j];
    __syncthreads();

#pragma unroll 1
    for (int c = 0; c < 8; c++) {
        // issue loads for next chunk
        if (c < 7) {
            const float* xc = xb + (size_t)(c + 1) * 32 * HW_;
#pragma unroll
            for (int j = 0; j < 8; j++) {
                const int f4 = tid + j * 256;
                const int k  = f4 >> 6;
                const int p4 = f4 & 63;
                stage[j] = *(const float4*)(xc + (size_t)k * HW_ + p4 * 4);
            }
        }

        const float* xs = x_sh[c & 1];
        const float* wc = w_sh + c * 32;     // w_sh[o*256 + c*32 + k]
#pragma unroll
        for (int k = 0; k < 32; k++) {
            const float w0 = wc[(og * 4 + 0) * C_ + k];
            const float w1 = wc[(og * 4 + 1) * C_ + k];
            const float w2 = wc[(og * 4 + 2) * C_ + k];
            const float w3 = wc[(og * 4 + 3) * C_ + k];
            const float4 xa = *(const float4*)&xs[k * 256 + pg * 8];
            const float4 xbv = *(const float4*)&xs[k * 256 + pg * 8 + 4];
            const float xr[8] = {xa.x, xa.y, xa.z, xa.w, xbv.x, xbv.y, xbv.z, xbv.w};
#pragma unroll
            for (int i = 0; i < 8; i++) {
                acc[0][i] = fmaf(w0, xr[i], acc[0][i]);
                acc[1][i] = fmaf(w1, xr[i], acc[1][i]);
                acc[2][i] = fmaf(w2, xr[i], acc[2][i]);
                acc[3][i] = fmaf(w3, xr[i], acc[3][i]);
            }
        }

        if (c < 7) {
            float4* dst = (float4*)x_sh[(c + 1) & 1];
#pragma unroll
            for (int j = 0; j < 8; j++)
                dst[tid + j * 256] = stage[j];
            __syncthreads();
        }
    }

    // Transpose acc through SMEM: sm_t[pos][o], stride 33 (conflict-free read)
    __syncthreads();
    float* sm_t = x_sh[0];                   // reuse: 256*33 = 8448 floats < 16384
#pragma unroll
    for (int j = 0; j < 4; j++)
#pragma unroll
        for (int i = 0; i < 8; i++)
            sm_t[(pg * 8 + i) * 33 + og * 4 + j] = acc[j][i];
    __syncthreads();

    // Epilogue: thread t owns position t
    const int pos = posb + tid;
    const int h = pos / W_;
    const int w = pos % W_;
    const float wf = (float)w, hf = (float)h;
    const float* row = sm_t + tid * 33;

#pragma unroll
    for (int gi = 0; gi < G_; gi++) {
#pragma unroll
        for (int sy = 0; sy < 2; sy++) {
#pragma unroll
            for (int sx = 0; sx < 2; sx++) {
                const int idx = gi * 4 + sy * 2 + sx;
                float ix = wf + (row[idx]      + b_sh[idx])      * 0.25f;
                float iy = hf + (row[16 + idx] + b_sh[16 + idx]) * 0.25f;
                ix = fminf(fmaxf(ix, 0.f), (float)(W_ - 1));
                iy = fminf(fmaxf(iy, 0.f), (float)(H_ - 1));
                const int n  = b * G_ + gi;
                const int oy = 2 * h + sy;
                const int ox = 2 * w + sx;
                g_coords[((size_t)n * HO_ + oy) * WO_ + ox] = make_float2(ix, iy);
            }
        }
    }
}

// ---------------------------------------------------------------------------
// Kernel 2: bilinear gather from SMEM tile (R3 version, best measured).
// Block = (n, 4 output rows, full 192 width), 256 threads, 3 px/thread.
// Tile: 4 input rows x 96 (stride 100), 8 channels per chunk = 12.8 KB.
// ---------------------------------------------------------------------------
#define TR   4
#define TSD  100
#define CCH  8
#define PXPT 3

__global__ __launch_bounds__(256) void dysample_sample_kernel(
    const float* __restrict__ x,
    float* __restrict__ out)
{
    __shared__ __align__(16) float tile[CCH * TR * TSD];   // 12.8 KB

    const int tid = threadIdx.x;
    const int n   = blockIdx.y;
    const int b   = n >> 2;
    const int gi  = n & 3;
    const int oy0 = blockIdx.x * 4;
    const int h0  = oy0 >> 1;

    int r0 = h0 - 1;
    if (r0 < 0) r0 = 0;
    if (r0 > H_ - TR) r0 = H_ - TR;   // 92

    float4 wts[PXPT];
    int a00[PXPT], a01[PXPT], a10[PXPT], a11[PXPT];
    int obase[PXPT];
    unsigned fbmask = 0;

#pragma unroll
    for (int k = 0; k < PXPT; k++) {
        const int p   = tid + k * 256;
        const int ox  = p % WO_;
        const int oyr = p / WO_;
        const float2 c = g_coords[((size_t)n * HO_ + oy0 + oyr) * WO_ + ox];
        const float x0f = floorf(c.x), y0f = floorf(c.y);
        const int xi0 = (int)x0f, yi0 = (int)y0f;
        const float wx = c.x - x0f, wy = c.y - y0f;
        const int xi1 = min(xi0 + 1, W_ - 1);
        const int yi1 = min(yi0 + 1, H_ - 1);
        wts[k] = make_float4((1.f - wy) * (1.f - wx), (1.f - wy) * wx,
                             wy * (1.f - wx),         wy * wx);
        const bool intile = (yi0 >= r0) && (yi1 <= r0 + TR - 1);
        if (intile) {
            const int dxc = xi1 - xi0;
            a00[k] = (yi0 - r0) * TSD + xi0;
            a01[k] = a00[k] + dxc;
            a10[k] = (yi1 - r0) * TSD + xi0;
            a11[k] = a10[k] + dxc;
        } else {
            fbmask |= 1u << k;
            a00[k] = yi0 * W_ + xi0;
            a01[k] = yi0 * W_ + xi1;
            a10[k] = yi1 * W_ + xi0;
            a11[k] = yi1 * W_ + xi1;
        }
        obase[k] = (oy0 + oyr) * WO_ + ox;
    }

    const int ch0 = b * C_ + gi * CG_;
    const float* xg = x + (size_t)ch0 * HW_;
    float* og = out + (size_t)ch0 * HOWO_;

#pragma unroll 1
    for (int cb = 0; cb < CG_; cb += CCH) {
        __syncthreads();
#pragma unroll
        for (int i = tid; i < CCH * TR * 24; i += 256) {
            const int ch  = i / (TR * 24);
            const int rem = i % (TR * 24);
            const int row = rem / 24;
            const int c4  = rem % 24;
            const float4 v = *(const float4*)(xg + (size_t)(cb + ch) * HW_
                                              + (r0 + row) * W_ + c4 * 4);
            *(float4*)&tile[ch * (TR * TSD) + row * TSD + c4 * 4] = v;
        }
        __syncthreads();

#pragma unroll
        for (int k = 0; k < PXPT; k++) {
            const float4 wv = wts[k];
            float* ob = og + (size_t)cb * HOWO_ + obase[k];
            if (!((fbmask >> k) & 1u)) {
                const int i0 = a00[k], i1 = a01[k], i2 = a10[k], i3 = a11[k];
#pragma unroll
                for (int ch = 0; ch < CCH; ch++) {
                    const float* tc = tile + ch * (TR * TSD);
                    float v = wv.x * tc[i0];
                    v = fmaf(wv.y, tc[i1], v);
                    v = fmaf(wv.z, tc[i2], v);
                    v = fmaf(wv.w, tc[i3], v);
                    ob[(size_t)ch * HOWO_] = v;
                }
            } else {
                const int i0 = a00[k], i1 = a01[k], i2 = a10[k], i3 = a11[k];
#pragma unroll
                for (int ch = 0; ch < CCH; ch++) {
                    const float* gc = xg + (size_t)(cb + ch) * HW_;
                    float v = wv.x * __ldg(gc + i0);
                    v = fmaf(wv.y, __ldg(gc + i1), v);
                    v = fmaf(wv.z, __ldg(gc + i2), v);
                    v = fmaf(wv.w, __ldg(gc + i3), v);
                    ob[(size_t)ch * HOWO_] = v;
                }
            }
        }
    }
}

// ---------------------------------------------------------------------------
extern "C" void kernel_launch(void* const* d_in, const int* in_sizes, int n_in,
                              void* d_out, int out_size)
{
    const float* x     = (const float*)d_in[0];
    const float* w_off = (const float*)d_in[1];
    const float* b_off = (const float*)d_in[2];
    float* out = (float*)d_out;

    dysample_offset_kernel<<<B_ * HW_ / 256, 256>>>(x, w_off, b_off);
    dysample_sample_kernel<<<dim3(48, B_ * G_), 256>>>(x, out);
}

// round 12
// speedup vs baseline: 1.3564x; 1.0546x over previous
#include <cuda_runtime.h>
#include <cuda_bf16.h>
#include <cstdint>

#define B_   8
#define C_   256
#define H_   96
#define W_   96
#define HW_  (H_*W_)          // 9216
#define G_   4
#define CG_  64
#define HO_  192
#define WO_  192
#define HOWO_ (HO_*WO_)
#define NOUT_ 32

// Scratch coords (ix, iy) per output pixel, layout [n][oy][ox]
__device__ __align__(16) float2 g_coords[B_ * G_ * HO_ * WO_];   // 9.4 MB

// ---------------------------------------------------------------------------
// Kernel 1: offset head as register-tiled GEMM (R11, measured ~50us).
// ---------------------------------------------------------------------------
__global__ __launch_bounds__(256) void dysample_offset_kernel(
    const float* __restrict__ x,
    const float* __restrict__ w_off,
    const float* __restrict__ b_off)
{
    __shared__ __align__(16) float w_sh[NOUT_ * C_];     // 32 KB [o][k]
    __shared__ float b_sh[NOUT_];
    __shared__ __align__(16) float x_sh[2][32 * 256];    // 64 KB, [buf][k][pos]

    const int tid = threadIdx.x;
#pragma unroll
    for (int i = 0; i < 8; i++)
        ((float4*)w_sh)[tid + i * 256] = ((const float4*)w_off)[tid + i * 256];
    if (tid < NOUT_) b_sh[tid] = b_off[tid];

    const int pos0 = blockIdx.x * 256;
    const int b    = pos0 / HW_;
    const int posb = pos0 % HW_;
    const float* xb = x + (size_t)b * C_ * HW_ + posb;

    const int og = tid >> 5;
    const int pg = tid & 31;

    float acc[4][8];
#pragma unroll
    for (int j = 0; j < 4; j++)
#pragma unroll
        for (int i = 0; i < 8; i++) acc[j][i] = 0.f;

    float4 stage[8];
#pragma unroll
    for (int j = 0; j < 8; j++) {
        const int f4 = tid + j * 256;
        const int k  = f4 >> 6;
        const int p4 = f4 & 63;
        stage[j] = *(const float4*)(xb + (size_t)k * HW_ + p4 * 4);
    }
#pragma unroll
    for (int j = 0; j < 8; j++)
        ((float4*)x_sh[0])[tid + j * 256] = stage[j];
    __syncthreads();

#pragma unroll 1
    for (int c = 0; c < 8; c++) {
        if (c < 7) {
            const float* xc = xb + (size_t)(c + 1) * 32 * HW_;
#pragma unroll
            for (int j = 0; j < 8; j++) {
                const int f4 = tid + j * 256;
                const int k  = f4 >> 6;
                const int p4 = f4 & 63;
                stage[j] = *(const float4*)(xc + (size_t)k * HW_ + p4 * 4);
            }
        }

        const float* xs = x_sh[c & 1];
        const float* wc = w_sh + c * 32;
#pragma unroll
        for (int k = 0; k < 32; k++) {
            const float w0 = wc[(og * 4 + 0) * C_ + k];
            const float w1 = wc[(og * 4 + 1) * C_ + k];
            const float w2 = wc[(og * 4 + 2) * C_ + k];
            const float w3 = wc[(og * 4 + 3) * C_ + k];
            const float4 xa = *(const float4*)&xs[k * 256 + pg * 8];
            const float4 xbv = *(const float4*)&xs[k * 256 + pg * 8 + 4];
            const float xr[8] = {xa.x, xa.y, xa.z, xa.w, xbv.x, xbv.y, xbv.z, xbv.w};
#pragma unroll
            for (int i = 0; i < 8; i++) {
                acc[0][i] = fmaf(w0, xr[i], acc[0][i]);
                acc[1][i] = fmaf(w1, xr[i], acc[1][i]);
                acc[2][i] = fmaf(w2, xr[i], acc[2][i]);
                acc[3][i] = fmaf(w3, xr[i], acc[3][i]);
            }
        }

        if (c < 7) {
            float4* dst = (float4*)x_sh[(c + 1) & 1];
#pragma unroll
            for (int j = 0; j < 8; j++)
                dst[tid + j * 256] = stage[j];
            __syncthreads();
        }
    }

    __syncthreads();
    float* sm_t = x_sh[0];
#pragma unroll
    for (int j = 0; j < 4; j++)
#pragma unroll
        for (int i = 0; i < 8; i++)
            sm_t[(pg * 8 + i) * 33 + og * 4 + j] = acc[j][i];
    __syncthreads();

    const int pos = posb + tid;
    const int h = pos / W_;
    const int w = pos % W_;
    const float wf = (float)w, hf = (float)h;
    const float* row = sm_t + tid * 33;

#pragma unroll
    for (int gi = 0; gi < G_; gi++) {
#pragma unroll
        for (int sy = 0; sy < 2; sy++) {
#pragma unroll
            for (int sx = 0; sx < 2; sx++) {
                const int idx = gi * 4 + sy * 2 + sx;
                float ix = wf + (row[idx]      + b_sh[idx])      * 0.25f;
                float iy = hf + (row[16 + idx] + b_sh[16 + idx]) * 0.25f;
                ix = fminf(fmaxf(ix, 0.f), (float)(W_ - 1));
                iy = fminf(fmaxf(iy, 0.f), (float)(H_ - 1));
                const int n  = b * G_ + gi;
                const int oy = 2 * h + sy;
                const int ox = 2 * w + sx;
                g_coords[((size_t)n * HO_ + oy) * WO_ + ox] = make_float2(ix, iy);
            }
        }
    }
}

// ---------------------------------------------------------------------------
// Kernel 2: bilinear gather, channel-interleaved float4 tile, double-buffered.
// Block = (n, 4 output rows x 192), 256 thr, 3 px/thread.
// Tile cell [r][c] = float4 of channels cb..cb+3; one LDS.128 per tap serves
// 4 channels. One barrier per 4-channel chunk (16 total).
// ---------------------------------------------------------------------------
#define TR    4
#define TST4  97

__global__ __launch_bounds__(256) void dysample_sample_kernel(
    const float* __restrict__ x,
    float* __restrict__ out)
{
    __shared__ __align__(16) float4 tile[2][TR * TST4];   // 12.4 KB

    const int tid = threadIdx.x;
    const int n   = blockIdx.y;
    const int b   = n >> 2;
    const int gi  = n & 3;
    const int oy0 = blockIdx.x * 4;

    int r0 = (oy0 >> 1) - 1;
    if (r0 < 0) r0 = 0;
    if (r0 > H_ - TR) r0 = H_ - TR;          // 92
    const int r1 = r0 + TR - 1;

    // Per-pixel state
    float4 wts[3];
    int t00[3], t01[3], t10[3], t11[3];
    int obase[3];
    unsigned fbmask = 0;

#pragma unroll
    for (int k = 0; k < 3; k++) {
        const int p   = tid + k * 256;
        const int oyr = p / WO_;
        const int ox  = p % WO_;
        const float2 c = g_coords[((size_t)n * HO_ + oy0 + oyr) * WO_ + ox];
        const float x0f = floorf(c.x), y0f = floorf(c.y);
        const int xi0 = (int)x0f, yi0 = (int)y0f;
        const float wx = c.x - x0f, wy = c.y - y0f;
        const int xi1 = min(xi0 + 1, W_ - 1);
        const int yi1 = min(yi0 + 1, H_ - 1);
        wts[k] = make_float4((1.f - wy) * (1.f - wx), (1.f - wy) * wx,
                             wy * (1.f - wx),         wy * wx);
        if (yi0 >= r0 && yi1 <= r1) {
            t00[k] = (yi0 - r0) * TST4 + xi0;
            t01[k] = (yi0 - r0) * TST4 + xi1;
            t10[k] = (yi1 - r0) * TST4 + xi0;
            t11[k] = (yi1 - r0) * TST4 + xi1;
        } else {
            fbmask |= 1u << k;
            t00[k] = yi0 * W_ + xi0;
            t01[k] = yi0 * W_ + xi1;
            t10[k] = yi1 * W_ + xi0;
            t11[k] = yi1 * W_ + xi1;
        }
        obase[k] = (oy0 + oyr) * WO_ + ox;
    }

    const int ch0 = b * C_ + gi * CG_;
    const float* xg = x + (size_t)ch0 * HW_;
    float* og = out + (size_t)ch0 * HOWO_;

    // Fill-task geometry: cell i = (row, col); thread does i=tid and i=tid+256
    const int frow1 = tid / 96, fcol1 = tid % 96;
    const int i2    = tid + 256;
    const int frow2 = i2 / 96,  fcol2 = i2 % 96;    // valid if tid < 128
    const bool has2 = (i2 < TR * 96);

    float s1[4], s2[4];

    // Prologue: stage + STS chunk 0
    {
        const float* a1 = xg + (r0 + frow1) * W_ + fcol1;
#pragma unroll
        for (int j = 0; j < 4; j++) s1[j] = __ldg(a1 + j * HW_);
        if (has2) {
            const float* a2 = xg + (r0 + frow2) * W_ + fcol2;
#pragma unroll
            for (int j = 0; j < 4; j++) s2[j] = __ldg(a2 + j * HW_);
        }
        tile[0][frow1 * TST4 + fcol1] = make_float4(s1[0], s1[1], s1[2], s1[3]);
        if (has2)
            tile[0][frow2 * TST4 + fcol2] = make_float4(s2[0], s2[1], s2[2], s2[3]);
    }
    __syncthreads();

#pragma unroll 1
    for (int c4 = 0; c4 < 16; c4++) {
        // Stage loads for next chunk (overlaps compute below)
        if (c4 < 15) {
            const float* xc = xg + (size_t)(c4 + 1) * 4 * HW_;
            const float* a1 = xc + (r0 + frow1) * W_ + fcol1;
#pragma unroll
            for (int j = 0; j < 4; j++) s1[j] = __ldg(a1 + j * HW_);
            if (has2) {
                const float* a2 = xc + (r0 + frow2) * W_ + fcol2;
#pragma unroll
                for (int j = 0; j < 4; j++) s2[j] = __ldg(a2 + j * HW_);
            }
        }

        const float4* tb = tile[c4 & 1];
        float* oc = og + (size_t)c4 * 4 * HOWO_;

#pragma unroll
        for (int k = 0; k < 3; k++) {
            const float4 wv = wts[k];
            float* op = oc + obase[k];
            if (!((fbmask >> k) & 1u)) {
                const float4 v00 = tb[t00[k]];
                const float4 v01 = tb[t01[k]];
                const float4 v10 = tb[t10[k]];
                const float4 v11 = tb[t11[k]];
                float r0v = wv.x * v00.x;
                float r1v = wv.x * v00.y;
                float r2v = wv.x * v00.z;
                float r3v = wv.x * v00.w;
                r0v = fmaf(wv.y, v01.x, r0v);
                r1v = fmaf(wv.y, v01.y, r1v);
                r2v = fmaf(wv.y, v01.z, r2v);
                r3v = fmaf(wv.y, v01.w, r3v);
                r0v = fmaf(wv.z, v10.x, r0v);
                r1v = fmaf(wv.z, v10.y, r1v);
                r2v = fmaf(wv.z, v10.z, r2v);
                r3v = fmaf(wv.z, v10.w, r3v);
                r0v = fmaf(wv.w, v11.x, r0v);
                r1v = fmaf(wv.w, v11.y, r1v);
                r2v = fmaf(wv.w, v11.z, r2v);
                r3v = fmaf(wv.w, v11.w, r3v);
                op[0]                 = r0v;
                op[(size_t)HOWO_]     = r1v;
                op[(size_t)2 * HOWO_] = r2v;
                op[(size_t)3 * HOWO_] = r3v;
            } else {
                const float* xc = xg + (size_t)c4 * 4 * HW_;
#pragma unroll
                for (int ch = 0; ch < 4; ch++) {
                    const float* gc = xc + (size_t)ch * HW_;
                    float v = wv.x * __ldg(gc + t00[k]);
                    v = fmaf(wv.y, __ldg(gc + t01[k]), v);
                    v = fmaf(wv.z, __ldg(gc + t10[k]), v);
                    v = fmaf(wv.w, __ldg(gc + t11[k]), v);
                    op[(size_t)ch * HOWO_] = v;
                }
            }
        }

        // Commit next chunk to the other buffer (its last readers finished
        // one full iteration ago), then barrier before it is consumed.
        if (c4 < 15) {
            float4* td = tile[(c4 + 1) & 1];
            td[frow1 * TST4 + fcol1] = make_float4(s1[0], s1[1], s1[2], s1[3]);
            if (has2)
                td[frow2 * TST4 + fcol2] = make_float4(s2[0], s2[1], s2[2], s2[3]);
            __syncthreads();
        }
    }
}

// ---------------------------------------------------------------------------
extern "C" void kernel_launch(void* const* d_in, const int* in_sizes, int n_in,
                              void* d_out, int out_size)
{
    const float* x     = (const float*)d_in[0];
    const float* w_off = (const float*)d_in[1];
    const float* b_off = (const float*)d_in[2];
    float* out = (float*)d_out;

    dysample_offset_kernel<<<B_ * HW_ / 256, 256>>>(x, w_off, b_off);
    dysample_sample_kernel<<<dim3(48, B_ * G_), 256>>>(x, out);
}